// round 12
// baseline (speedup 1.0000x reference)
#include <cuda_runtime.h>
#include <cuda_fp16.h>
#include <cstdint>

#define NN 8192
#define DD 128
#define PP 4
#define KK 512            // P*D concatenated feature dim
#define EPS 0.3f
#define EMAX (1 << 19)
#define CAND_MAX (1 << 20)
#define DESCALE 0.00390625f      // 2^-8 (each operand scaled by 16)
#define HBITS 20
#define HSIZE (1 << HBITS)
#define HMASK (HSIZE - 1)
#define ZBLK 64                  // hash-zero blocks fused into buildY

// Scratch (allocation banned -> __device__ globals)
__device__ __half d_H[(size_t)NN * KK];    //  8 MB: fp16(y)*16 (SYRK operand)
__device__ float  d_Yf[(size_t)NN * KK];   // 16 MB: fp32 y (exact recompute)
__device__ float  d_nh[NN], d_nl[NN];      // per-row norms for error margin
__device__ int    d_hkey[HSIZE];           //  4 MB hash keys (0=empty, key+1)
__device__ float  d_hval[HSIZE];           //  4 MB hash values
__device__ float  d_val[EMAX];
__device__ int    d_ncand;
__device__ int2   d_cand[CAND_MAX];

// ---------------------------------------------------------------------------
__device__ __forceinline__ uint32_t smem_u32(const void* p) {
    uint32_t a;
    asm("{ .reg .u64 t; cvta.to.shared.u64 t, %1; cvt.u32.u64 %0, t; }" : "=r"(a) : "l"(p));
    return a;
}
__device__ __forceinline__ void ldsm_x4(uint32_t* r, uint32_t addr) {
    asm volatile("ldmatrix.sync.aligned.m8n8.x4.shared.b16 {%0,%1,%2,%3}, [%4];"
                 : "=r"(r[0]), "=r"(r[1]), "=r"(r[2]), "=r"(r[3]) : "r"(addr));
}
__device__ __forceinline__ void mma_acc(float* c, const uint32_t* a,
                                        uint32_t b0, uint32_t b1) {
    asm volatile(
        "mma.sync.aligned.m16n8k16.row.col.f32.f16.f16.f32 "
        "{%0,%1,%2,%3},{%4,%5,%6,%7},{%8,%9},{%0,%1,%2,%3};"
        : "+f"(c[0]), "+f"(c[1]), "+f"(c[2]), "+f"(c[3])
        : "r"(a[0]), "r"(a[1]), "r"(a[2]), "r"(a[3]), "r"(b0), "r"(b1));
}
__device__ __forceinline__ void mma_set(float* c, const uint32_t* a,
                                        uint32_t b0, uint32_t b1) {
    asm volatile(
        "mma.sync.aligned.m16n8k16.row.col.f32.f16.f16.f32 "
        "{%0,%1,%2,%3},{%4,%5,%6,%7},{%8,%9},{%10,%11,%12,%13};"
        : "=f"(c[0]), "=f"(c[1]), "=f"(c[2]), "=f"(c[3])
        : "r"(a[0]), "r"(a[1]), "r"(a[2]), "r"(a[3]), "r"(b0), "r"(b1),
          "f"(0.f), "f"(0.f), "f"(0.f), "f"(0.f));
}
#define CP_ASYNC16(dst, src) \
    asm volatile("cp.async.cg.shared.global [%0], [%1], 16;" :: "r"(dst), "l"(src))
#define CP_COMMIT() asm volatile("cp.async.commit_group;" ::: "memory")
#define CP_WAIT1()  asm volatile("cp.async.wait_group 1;" ::: "memory")

__device__ __forceinline__ uint32_t hash_slot(int key) {
    return ((uint32_t)key * 2654435761u) >> (32 - HBITS);
}
__device__ __forceinline__ float og_lookup(int key) {
    uint32_t s = hash_slot(key);
    while (d_hkey[s] != key + 1) s = (s + 1) & HMASK;
    return d_hval[s];
}

// ---------------------------------------------------------------------------
// buildY (+ fused hash zero): blocks [0,NN) build features; blocks
// [NN, NN+ZBLK) zero the og hash table and reset the candidate counter.
// ---------------------------------------------------------------------------
__global__ __launch_bounds__(512) void buildY_kernel(const float* __restrict__ x,
                                                     const float* __restrict__ wp) {
    if (blockIdx.x >= NN) {            // fused hash-zero path
        int zb = blockIdx.x - NN;
        int base = zb * (HSIZE / ZBLK);
        for (int s = threadIdx.x; s < HSIZE / ZBLK; s += 512) {
            d_hkey[base + s] = 0;
            d_hval[base + s] = 0.f;
        }
        if (zb == 0 && threadIdx.x == 0) d_ncand = 0;
        return;
    }
    int i = blockIdx.x;
    int tid = threadIdx.x;
    int p = tid >> 7, d = tid & 127;
    int widp = (tid >> 5) & 3;

    __shared__ float pred[PP][4];
    __shared__ float nred[16][2];

    float v = x[i * DD + d] * wp[p * DD + d];
    float s = v * v;
#pragma unroll
    for (int o = 16; o > 0; o >>= 1) s += __shfl_xor_sync(0xffffffffu, s, o);
    if ((tid & 31) == 0) pred[p][widp] = s;
    __syncthreads();

    float tot = pred[p][0] + pred[p][1] + pred[p][2] + pred[p][3];
    float inv = 0.5f / fmaxf(sqrtf(tot), 1e-12f);
    float yv = v * inv;
    float hf = __half2float(__float2half_rn(yv));
    float lo = yv - hf;
    // flush hazard: scaled hi below fp16 min-normal is flushed in HMMA
    float e = fabsf(lo) + ((fabsf(hf) < 3.815e-6f) ? fabsf(hf) : 0.f);
    int k = p * DD + d;
    d_H[(size_t)i * KK + k]  = __float2half_rn(hf * 16.0f);   // exact scale
    d_Yf[(size_t)i * KK + k] = yv;

    float hi2 = hf * hf, lo2 = e * e;
#pragma unroll
    for (int o = 16; o > 0; o >>= 1) {
        hi2 += __shfl_xor_sync(0xffffffffu, hi2, o);
        lo2 += __shfl_xor_sync(0xffffffffu, lo2, o);
    }
    int w = tid >> 5;
    if ((tid & 31) == 0) { nred[w][0] = hi2; nred[w][1] = lo2; }
    __syncthreads();
    if (tid == 0) {
        float h2 = 0.f, l2 = 0.f;
#pragma unroll
        for (int q = 0; q < 16; q++) { h2 += nred[q][0]; l2 += nred[q][1]; }
        d_nh[i] = sqrtf(h2);
        d_nl[i] = sqrtf(l2);
    }
}

// ---------------------------------------------------------------------------
// HMMA fp16 SYRK (K=512, hi-only) + fused edge scatter (extra blocks).
// Segmented accumulation, margin candidates, thresholded epilogue + mirror.
// ---------------------------------------------------------------------------
#define STAGES 3
#define KSTEP 64
#define NSTEPS (KK / KSTEP)        // 8
#define SEG 2
#define TILE_BYTES 16384           // 128 rows x 128B
#define STAGE_BYTES (2 * TILE_BYTES)
#define NTHREADS 512
#define NBLK (NN / 128)            // 64
#define NTRI (NBLK * (NBLK + 1) / 2)   // 2080

__global__ __launch_bounds__(NTHREADS, 1) void gemm_hmma_kernel(
        float* __restrict__ out, const int* __restrict__ oi,
        const float* __restrict__ ow, int E) {
    if (blockIdx.x >= NTRI) {      // fused scatter path (runs under the GEMM)
        int e = (blockIdx.x - NTRI) * NTHREADS + threadIdx.x;
        if (e < E) {
            int key = oi[e] * NN + oi[E + e];
            uint32_t s = hash_slot(key);
            while (true) {
                int prev = atomicCAS(&d_hkey[s], 0, key + 1);
                if (prev == 0 || prev == key + 1) {
                    atomicAdd(&d_hval[s], ow[e]);
                    break;
                }
                s = (s + 1) & HMASK;
            }
        }
        return;
    }

    // triangular index -> (bi, bj), bj >= bi
    int t = blockIdx.x;
    int r = (int)floorf((2.f * NBLK + 1.f -
                         sqrtf((2.f * NBLK + 1.f) * (2.f * NBLK + 1.f) - 8.f * t)) * 0.5f);
    #define TSTART(rr) ((rr) * NBLK - ((rr) * ((rr) - 1)) / 2)
    while (TSTART(r + 1) <= t) ++r;
    while (TSTART(r) > t) --r;
    int bi = r, bj = r + (t - TSTART(r));

    extern __shared__ char dsm[];
    uint32_t smem = smem_u32(dsm);
    int tid = threadIdx.x, wid = tid >> 5, lane = tid & 31;
    int wr = wid >> 2, wc = wid & 3;   // 4x4 warp grid: 32x32 warp tiles

    const __half* Ag = d_H + (size_t)bi * 128 * KK;
    const __half* Bg = d_H + (size_t)bj * 128 * KK;

    auto prefetch = [&](int ks) {
        if (ks < NSTEPS) {
            uint32_t sa = smem + (ks % STAGES) * STAGE_BYTES;
            uint32_t sb = sa + TILE_BYTES;
            const __half* ga = Ag + ks * KSTEP;
            const __half* gb = Bg + ks * KSTEP;
#pragma unroll
            for (int l = 0; l < 2; l++) {
                int id = l * NTHREADS + tid;   // 1024 16B-chunks per matrix
                int rr = id >> 3, c = id & 7;
                uint32_t off = rr * 128 + ((c ^ (rr & 7)) << 4);  // SW128 swizzle
                CP_ASYNC16(sa + off, ga + (size_t)rr * KK + c * 8);
                CP_ASYNC16(sb + off, gb + (size_t)rr * KK + c * 8);
            }
        }
        CP_COMMIT();
    };

    float acc[2][4][4];
    float csum[2][4][4];
#pragma unroll
    for (int mt = 0; mt < 2; mt++)
#pragma unroll
        for (int nt = 0; nt < 4; nt++)
#pragma unroll
            for (int q = 0; q < 4; q++) csum[mt][nt][q] = 0.f;

    int aRow = lane & 15;
    int aHalf = lane >> 4;
    int bRow = (lane & 7) + ((lane >> 4) << 3);
    int bHalf = (lane >> 3) & 1;

    prefetch(0);
    prefetch(1);

    for (int ks = 0; ks < NSTEPS; ks++) {
        CP_WAIT1();
        __syncthreads();
        prefetch(ks + 2);

        uint32_t sa = smem + (ks % STAGES) * STAGE_BYTES;
        uint32_t sb = sa + TILE_BYTES;
        bool segStart = (ks % SEG) == 0;
#pragma unroll
        for (int k16 = 0; k16 < 4; k16++) {
            uint32_t a[2][4];
#pragma unroll
            for (int mt = 0; mt < 2; mt++) {
                int rr = wr * 32 + mt * 16 + aRow;
                int c = 2 * k16 + aHalf;
                ldsm_x4(a[mt], sa + rr * 128 + ((c ^ (rr & 7)) << 4));
            }
            uint32_t b[2][4];
#pragma unroll
            for (int np = 0; np < 2; np++) {
                int rr = wc * 32 + np * 16 + bRow;
                int c = 2 * k16 + bHalf;
                ldsm_x4(b[np], sb + rr * 128 + ((c ^ (rr & 7)) << 4));
            }
            if (segStart && k16 == 0) {
#pragma unroll
                for (int mt = 0; mt < 2; mt++)
#pragma unroll
                    for (int np = 0; np < 2; np++) {
                        mma_set(acc[mt][2 * np],     a[mt], b[np][0], b[np][1]);
                        mma_set(acc[mt][2 * np + 1], a[mt], b[np][2], b[np][3]);
                    }
            } else {
#pragma unroll
                for (int mt = 0; mt < 2; mt++)
#pragma unroll
                    for (int np = 0; np < 2; np++) {
                        mma_acc(acc[mt][2 * np],     a[mt], b[np][0], b[np][1]);
                        mma_acc(acc[mt][2 * np + 1], a[mt], b[np][2], b[np][3]);
                    }
            }
        }
        if ((ks % SEG) == SEG - 1) {   // RN drain
#pragma unroll
            for (int mt = 0; mt < 2; mt++)
#pragma unroll
                for (int nt = 0; nt < 4; nt++)
#pragma unroll
                    for (int q = 0; q < 4; q++)
                        csum[mt][nt][q] += acc[mt][nt][q];
        }
    }

    // Epilogue: de-scale, margin-check (push candidate), threshold, mirror
    int g = lane >> 2, tg = lane & 3;
    float nhj[4][2], nlj[4][2];
#pragma unroll
    for (int nt = 0; nt < 4; nt++)
#pragma unroll
        for (int q2 = 0; q2 < 2; q2++) {
            int gj = bj * 128 + wc * 32 + nt * 8 + tg * 2 + q2;
            nhj[nt][q2] = d_nh[gj];
            nlj[nt][q2] = d_nl[gj];
        }
#pragma unroll
    for (int mt = 0; mt < 2; mt++) {
#pragma unroll
        for (int h = 0; h < 2; h++) {
            int gi = bi * 128 + wr * 32 + mt * 16 + h * 8 + g;
            float nhi = d_nh[gi], nli = d_nl[gi];
            float* rowp = out + (size_t)gi * NN + bj * 128 + wc * 32 + tg * 2;
#pragma unroll
            for (int nt = 0; nt < 4; nt++) {
                float s0 = csum[mt][nt][2 * h] * DESCALE;
                float s1 = csum[mt][nt][2 * h + 1] * DESCALE;
                int gj0 = bj * 128 + wc * 32 + nt * 8 + tg * 2;
                float m0 = nhi * nlj[nt][0] + nli * nhj[nt][0] + 4e-6f;
                float m1 = nhi * nlj[nt][1] + nli * nhj[nt][1] + 4e-6f;
                if (fabsf(s0 - EPS) < m0) {
                    int idx = atomicAdd(&d_ncand, 1);
                    if (idx < CAND_MAX) d_cand[idx] = make_int2(gi, gj0);
                }
                if (fabsf(s1 - EPS) < m1) {
                    int idx = atomicAdd(&d_ncand, 1);
                    if (idx < CAND_MAX) d_cand[idx] = make_int2(gi, gj0 + 1);
                }
                s0 = (s0 > EPS) ? s0 : 0.f;
                s1 = (s1 > EPS) ? s1 : 0.f;
                *(float2*)(rowp + nt * 8) = make_float2(s0, s1);
                if (bi != bj) {
                    out[(size_t)gj0 * NN + gi] = s0;
                    out[(size_t)(gj0 + 1) * NN + gi] = s1;
                }
            }
        }
    }
}

// ---------------------------------------------------------------------------
// Exact (fp64) recompute of margin candidates; patches entry + mirror
// ---------------------------------------------------------------------------
__global__ void patch_kernel(float* __restrict__ out) {
    int nc = d_ncand;
    if (nc > CAND_MAX) nc = CAND_MAX;
    int gw = (blockIdx.x * blockDim.x + threadIdx.x) >> 5;
    int lane = threadIdx.x & 31;
    int nw = (gridDim.x * blockDim.x) >> 5;
    for (int c = gw; c < nc; c += nw) {
        int2 e = d_cand[c];
        const float* yi = d_Yf + (size_t)e.x * KK;
        const float* yj = d_Yf + (size_t)e.y * KK;
        double a = 0.0;
        for (int k = lane; k < KK; k += 32) a += (double)yi[k] * (double)yj[k];
#pragma unroll
        for (int o = 16; o > 0; o >>= 1) a += __shfl_xor_sync(0xffffffffu, a, o);
        if (lane == 0) {
            float s = (float)a;
            float sg = (s > EPS) ? s : 0.f;
            out[(size_t)e.x * NN + e.y] = sg;
            out[(size_t)e.y * NN + e.x] = sg;
        }
    }
}

// ---------------------------------------------------------------------------
// Per-edge purification fixup (race-free, duplicate-idempotent)
// ---------------------------------------------------------------------------
__global__ void edge_fix_a(const int* __restrict__ oi,
                           const float* __restrict__ out, int E) {
    int e = blockIdx.x * blockDim.x + threadIdx.x;
    if (e >= E) return;
    int i = oi[e], j = oi[E + e];
    float og = og_lookup(i * NN + j);
    float so = out[(size_t)i * NN + j];   // sim_g (patched -> decisions exact)
    float purif = 0.f;
    bool need_exact;
    if (so == 0.f) {
        // s <= eps certain; s*og > eps possible only when og > 1 (duplicates)
        need_exact = (og > 1.0f);
    } else {
        float m = d_nh[i] * d_nl[j] + d_nl[i] * d_nh[j] + 4e-6f;
        need_exact = fabsf(so * og - EPS) < m * og + 1e-6f;
        if (!need_exact) purif = (so * og > EPS) ? og : 0.f;
    }
    if (need_exact) {
        const float* yi = d_Yf + (size_t)i * KK;
        const float* yj = d_Yf + (size_t)j * KK;
        double a = 0.0;
        for (int k = 0; k < KK; k++) a += (double)yi[k] * (double)yj[k];
        float s = (float)a;
        purif = (s * og > EPS) ? og : 0.f;
    }
    d_val[e] = so + purif;
}
__global__ void edge_fix_b(const int* __restrict__ oi, float* __restrict__ out, int E) {
    int e = blockIdx.x * blockDim.x + threadIdx.x;
    if (e >= E) return;
    out[(size_t)oi[e] * NN + oi[E + e]] = d_val[e];
}

// ---------------------------------------------------------------------------
extern "C" void kernel_launch(void* const* d_in, const int* in_sizes, int n_in,
                              void* d_out, int out_size) {
    const float* x  = (const float*)d_in[0];
    const int*   oi = (const int*)d_in[1];
    const float* ow = (const float*)d_in[2];
    const float* wp = (const float*)d_in[3];
    float* out = (float*)d_out;
    int E = in_sizes[2];

    cudaFuncSetAttribute(gemm_hmma_kernel,
                         cudaFuncAttributeMaxDynamicSharedMemorySize,
                         STAGES * STAGE_BYTES);

    int scatBlocks = (E + NTHREADS - 1) / NTHREADS;
    buildY_kernel<<<NN + ZBLK, 512>>>(x, wp);
    gemm_hmma_kernel<<<NTRI + scatBlocks, NTHREADS, STAGES * STAGE_BYTES>>>(out, oi, ow, E);
    patch_kernel<<<256, 256>>>(out);
    edge_fix_a<<<(E + 255) / 256, 256>>>(oi, out, E);
    edge_fix_b<<<(E + 255) / 256, 256>>>(oi, out, E);
}

// round 16
// speedup vs baseline: 1.6429x; 1.6429x over previous
#include <cuda_runtime.h>
#include <cuda_fp16.h>
#include <cstdint>

#define NN 8192
#define DD 128
#define PP 4
#define KK 512            // P*D concatenated feature dim
#define EPS 0.3f
#define EMAX (1 << 19)
#define CAND_MAX (1 << 20)
#define ECAND_MAX (1 << 18)
#define DESCALE 0.00390625f      // 2^-8 (each operand scaled by 16)

// Scratch (allocation banned -> __device__ globals)
__device__ __half d_H[(size_t)NN * KK];    //  8 MB: fp16(y)*16 (SYRK operand)
__device__ float  d_Yf[(size_t)NN * KK];   // 16 MB: fp32 y (exact recompute)
__device__ float  d_nh[NN], d_nl[NN];      // per-row norms for error margin
__device__ float  d_og[(size_t)NN * NN];   // only edge positions ever touched
__device__ float  d_val[EMAX];
__device__ int    d_ncand;                 // sim margin candidates
__device__ int2   d_cand[CAND_MAX];
__device__ int    d_necand;                // edge exact-path candidates
__device__ int    d_ecand[ECAND_MAX];

// ---------------------------------------------------------------------------
__device__ __forceinline__ uint32_t smem_u32(const void* p) {
    uint32_t a;
    asm("{ .reg .u64 t; cvta.to.shared.u64 t, %1; cvt.u32.u64 %0, t; }" : "=r"(a) : "l"(p));
    return a;
}
__device__ __forceinline__ void ldsm_x4(uint32_t* r, uint32_t addr) {
    asm volatile("ldmatrix.sync.aligned.m8n8.x4.shared.b16 {%0,%1,%2,%3}, [%4];"
                 : "=r"(r[0]), "=r"(r[1]), "=r"(r[2]), "=r"(r[3]) : "r"(addr));
}
__device__ __forceinline__ void mma_acc(float* c, const uint32_t* a,
                                        uint32_t b0, uint32_t b1) {
    asm volatile(
        "mma.sync.aligned.m16n8k16.row.col.f32.f16.f16.f32 "
        "{%0,%1,%2,%3},{%4,%5,%6,%7},{%8,%9},{%0,%1,%2,%3};"
        : "+f"(c[0]), "+f"(c[1]), "+f"(c[2]), "+f"(c[3])
        : "r"(a[0]), "r"(a[1]), "r"(a[2]), "r"(a[3]), "r"(b0), "r"(b1));
}
__device__ __forceinline__ void mma_set(float* c, const uint32_t* a,
                                        uint32_t b0, uint32_t b1) {
    asm volatile(
        "mma.sync.aligned.m16n8k16.row.col.f32.f16.f16.f32 "
        "{%0,%1,%2,%3},{%4,%5,%6,%7},{%8,%9},{%10,%11,%12,%13};"
        : "=f"(c[0]), "=f"(c[1]), "=f"(c[2]), "=f"(c[3])
        : "r"(a[0]), "r"(a[1]), "r"(a[2]), "r"(a[3]), "r"(b0), "r"(b1),
          "f"(0.f), "f"(0.f), "f"(0.f), "f"(0.f));
}
#define CP_ASYNC16(dst, src) \
    asm volatile("cp.async.cg.shared.global [%0], [%1], 16;" :: "r"(dst), "l"(src))
#define CP_COMMIT() asm volatile("cp.async.commit_group;" ::: "memory")
#define CP_WAIT1()  asm volatile("cp.async.wait_group 1;" ::: "memory")

// ---------------------------------------------------------------------------
// Edge prep (no dense memset; resets both candidate counters)
// ---------------------------------------------------------------------------
__global__ void zero_edges_kernel(const int* __restrict__ oi, int E) {
    int e = blockIdx.x * blockDim.x + threadIdx.x;
    if (e == 0) { d_ncand = 0; d_necand = 0; }
    if (e < E) d_og[(size_t)oi[e] * NN + oi[E + e]] = 0.f;
}
__global__ void scatter_kernel(const int* __restrict__ oi,
                               const float* __restrict__ ow, int E) {
    int e = blockIdx.x * blockDim.x + threadIdx.x;
    if (e < E) atomicAdd(&d_og[(size_t)oi[e] * NN + oi[E + e]], ow[e]);
}

// ---------------------------------------------------------------------------
// Build: y = 0.5*(x*w)/||x*w||; H = fp16(y)*16; Yf = fp32 y; norms for margin
// ---------------------------------------------------------------------------
__global__ void buildY_kernel(const float* __restrict__ x,
                              const float* __restrict__ wp) {
    int i = blockIdx.x;
    int d = threadIdx.x;   // 128 threads
    float xv = x[i * DD + d];
    __shared__ float sred[4], hred[4], lred[4];
    float hi2 = 0.f, lo2 = 0.f;
#pragma unroll
    for (int p = 0; p < PP; p++) {
        float v = xv * wp[p * DD + d];
        float s = v * v;
#pragma unroll
        for (int o = 16; o > 0; o >>= 1) s += __shfl_xor_sync(0xffffffffu, s, o);
        if ((d & 31) == 0) sred[d >> 5] = s;
        __syncthreads();
        float tot = sred[0] + sred[1] + sred[2] + sred[3];
        float inv = 0.5f / fmaxf(sqrtf(tot), 1e-12f);
        float yv = v * inv;
        float hf = __half2float(__float2half_rn(yv));
        float lo = yv - hf;
        // flush hazard: scaled hi below fp16 min-normal is flushed in HMMA
        float e = fabsf(lo) + ((fabsf(hf) < 3.815e-6f) ? fabsf(hf) : 0.f);
        int k = p * DD + d;
        d_H[(size_t)i * KK + k]  = __float2half_rn(hf * 16.0f);  // exact
        d_Yf[(size_t)i * KK + k] = yv;
        hi2 += hf * hf;
        lo2 += e * e;
        __syncthreads();
    }
#pragma unroll
    for (int o = 16; o > 0; o >>= 1) {
        hi2 += __shfl_xor_sync(0xffffffffu, hi2, o);
        lo2 += __shfl_xor_sync(0xffffffffu, lo2, o);
    }
    if ((d & 31) == 0) { hred[d >> 5] = hi2; lred[d >> 5] = lo2; }
    __syncthreads();
    if (d == 0) {
        d_nh[i] = sqrtf(hred[0] + hred[1] + hred[2] + hred[3]);
        d_nl[i] = sqrtf(lred[0] + lred[1] + lred[2] + lred[3]);
    }
}

// ---------------------------------------------------------------------------
// HMMA fp16 SYRK (K=512, hi-only), segmented accumulation, margin-based
// candidate detection, thresholded epilogue + mirror; triangular 1-D grid
// ---------------------------------------------------------------------------
#define STAGES 3
#define KSTEP 64
#define NSTEPS (KK / KSTEP)        // 8
#define SEG 2
#define TILE_BYTES 16384           // 128 rows x 128B
#define STAGE_BYTES (2 * TILE_BYTES)
#define NTHREADS 512
#define NBLK (NN / 128)            // 64
#define NTRI (NBLK * (NBLK + 1) / 2)   // 2080

__global__ __launch_bounds__(NTHREADS, 1) void gemm_hmma_kernel(float* __restrict__ out) {
    // triangular index -> (bi, bj), bj >= bi
    int t = blockIdx.x;
    int r = (int)floorf((2.f * NBLK + 1.f -
                         sqrtf((2.f * NBLK + 1.f) * (2.f * NBLK + 1.f) - 8.f * t)) * 0.5f);
    #define TSTART(rr) ((rr) * NBLK - ((rr) * ((rr) - 1)) / 2)
    while (TSTART(r + 1) <= t) ++r;
    while (TSTART(r) > t) --r;
    int bi = r, bj = r + (t - TSTART(r));

    extern __shared__ char dsm[];
    uint32_t smem = smem_u32(dsm);
    int tid = threadIdx.x, wid = tid >> 5, lane = tid & 31;
    int wr = wid >> 2, wc = wid & 3;   // 4x4 warp grid: 32x32 warp tiles

    const __half* Ag = d_H + (size_t)bi * 128 * KK;
    const __half* Bg = d_H + (size_t)bj * 128 * KK;

    auto prefetch = [&](int ks) {
        if (ks < NSTEPS) {
            uint32_t sa = smem + (ks % STAGES) * STAGE_BYTES;
            uint32_t sb = sa + TILE_BYTES;
            const __half* ga = Ag + ks * KSTEP;
            const __half* gb = Bg + ks * KSTEP;
#pragma unroll
            for (int l = 0; l < 2; l++) {
                int id = l * NTHREADS + tid;   // 1024 16B-chunks per matrix
                int rr = id >> 3, c = id & 7;
                uint32_t off = rr * 128 + ((c ^ (rr & 7)) << 4);  // SW128 swizzle
                CP_ASYNC16(sa + off, ga + (size_t)rr * KK + c * 8);
                CP_ASYNC16(sb + off, gb + (size_t)rr * KK + c * 8);
            }
        }
        CP_COMMIT();
    };

    float acc[2][4][4];
    float csum[2][4][4];
#pragma unroll
    for (int mt = 0; mt < 2; mt++)
#pragma unroll
        for (int nt = 0; nt < 4; nt++)
#pragma unroll
            for (int q = 0; q < 4; q++) csum[mt][nt][q] = 0.f;

    int aRow = lane & 15;
    int aHalf = lane >> 4;
    int bRow = (lane & 7) + ((lane >> 4) << 3);
    int bHalf = (lane >> 3) & 1;

    prefetch(0);
    prefetch(1);

    for (int ks = 0; ks < NSTEPS; ks++) {
        CP_WAIT1();
        __syncthreads();
        prefetch(ks + 2);

        uint32_t sa = smem + (ks % STAGES) * STAGE_BYTES;
        uint32_t sb = sa + TILE_BYTES;
        bool segStart = (ks % SEG) == 0;
#pragma unroll
        for (int k16 = 0; k16 < 4; k16++) {
            uint32_t a[2][4];
#pragma unroll
            for (int mt = 0; mt < 2; mt++) {
                int rr = wr * 32 + mt * 16 + aRow;
                int c = 2 * k16 + aHalf;
                ldsm_x4(a[mt], sa + rr * 128 + ((c ^ (rr & 7)) << 4));
            }
            uint32_t b[2][4];
#pragma unroll
            for (int np = 0; np < 2; np++) {
                int rr = wc * 32 + np * 16 + bRow;
                int c = 2 * k16 + bHalf;
                ldsm_x4(b[np], sb + rr * 128 + ((c ^ (rr & 7)) << 4));
            }
            if (segStart && k16 == 0) {
#pragma unroll
                for (int mt = 0; mt < 2; mt++)
#pragma unroll
                    for (int np = 0; np < 2; np++) {
                        mma_set(acc[mt][2 * np],     a[mt], b[np][0], b[np][1]);
                        mma_set(acc[mt][2 * np + 1], a[mt], b[np][2], b[np][3]);
                    }
            } else {
#pragma unroll
                for (int mt = 0; mt < 2; mt++)
#pragma unroll
                    for (int np = 0; np < 2; np++) {
                        mma_acc(acc[mt][2 * np],     a[mt], b[np][0], b[np][1]);
                        mma_acc(acc[mt][2 * np + 1], a[mt], b[np][2], b[np][3]);
                    }
            }
        }
        if ((ks % SEG) == SEG - 1) {   // RN drain
#pragma unroll
            for (int mt = 0; mt < 2; mt++)
#pragma unroll
                for (int nt = 0; nt < 4; nt++)
#pragma unroll
                    for (int q = 0; q < 4; q++)
                        csum[mt][nt][q] += acc[mt][nt][q];
        }
    }

    // Epilogue: de-scale, margin-check (push candidate), threshold, mirror
    int g = lane >> 2, tg = lane & 3;
    float nhj[4][2], nlj[4][2];
#pragma unroll
    for (int nt = 0; nt < 4; nt++)
#pragma unroll
        for (int q2 = 0; q2 < 2; q2++) {
            int gj = bj * 128 + wc * 32 + nt * 8 + tg * 2 + q2;
            nhj[nt][q2] = d_nh[gj];
            nlj[nt][q2] = d_nl[gj];
        }
#pragma unroll
    for (int mt = 0; mt < 2; mt++) {
#pragma unroll
        for (int h = 0; h < 2; h++) {
            int gi = bi * 128 + wr * 32 + mt * 16 + h * 8 + g;
            float nhi = d_nh[gi], nli = d_nl[gi];
            float* rowp = out + (size_t)gi * NN + bj * 128 + wc * 32 + tg * 2;
#pragma unroll
            for (int nt = 0; nt < 4; nt++) {
                float s0 = csum[mt][nt][2 * h] * DESCALE;
                float s1 = csum[mt][nt][2 * h + 1] * DESCALE;
                int gj0 = bj * 128 + wc * 32 + nt * 8 + tg * 2;
                float m0 = nhi * nlj[nt][0] + nli * nhj[nt][0] + 4e-6f;
                float m1 = nhi * nlj[nt][1] + nli * nhj[nt][1] + 4e-6f;
                if (fabsf(s0 - EPS) < m0) {
                    int idx = atomicAdd(&d_ncand, 1);
                    if (idx < CAND_MAX) d_cand[idx] = make_int2(gi, gj0);
                }
                if (fabsf(s1 - EPS) < m1) {
                    int idx = atomicAdd(&d_ncand, 1);
                    if (idx < CAND_MAX) d_cand[idx] = make_int2(gi, gj0 + 1);
                }
                s0 = (s0 > EPS) ? s0 : 0.f;
                s1 = (s1 > EPS) ? s1 : 0.f;
                *(float2*)(rowp + nt * 8) = make_float2(s0, s1);
                if (bi != bj) {
                    out[(size_t)gj0 * NN + gi] = s0;
                    out[(size_t)(gj0 + 1) * NN + gi] = s1;
                }
            }
        }
    }
}

// ---------------------------------------------------------------------------
// Exact (fp64, warp-collective) recompute of sim margin candidates
// ---------------------------------------------------------------------------
__global__ void patch_kernel(float* __restrict__ out) {
    int nc = d_ncand;
    if (nc > CAND_MAX) nc = CAND_MAX;
    int gw = (blockIdx.x * blockDim.x + threadIdx.x) >> 5;
    int lane = threadIdx.x & 31;
    int nw = (gridDim.x * blockDim.x) >> 5;
    for (int c = gw; c < nc; c += nw) {
        int2 e = d_cand[c];
        const float* yi = d_Yf + (size_t)e.x * KK;
        const float* yj = d_Yf + (size_t)e.y * KK;
        double a = 0.0;
        for (int k = lane; k < KK; k += 32) a += (double)yi[k] * (double)yj[k];
#pragma unroll
        for (int o = 16; o > 0; o >>= 1) a += __shfl_xor_sync(0xffffffffu, a, o);
        if (lane == 0) {
            float s = (float)a;
            float sg = (s > EPS) ? s : 0.f;
            out[(size_t)e.x * NN + e.y] = sg;
            out[(size_t)e.y * NN + e.x] = sg;
        }
    }
}

// ---------------------------------------------------------------------------
// Per-edge purification: FAST PATH ONLY. Uncertain edges -> d_ecand list.
// ---------------------------------------------------------------------------
__global__ void edge_fix_a(const int* __restrict__ oi,
                           const float* __restrict__ out, int E) {
    int e = blockIdx.x * blockDim.x + threadIdx.x;
    if (e >= E) return;
    int i = oi[e], j = oi[E + e];
    float og = d_og[(size_t)i * NN + j];
    float so = out[(size_t)i * NN + j];   // sim_g (patched -> decisions exact)
    float purif = 0.f;
    bool need_exact;
    if (so == 0.f) {
        // s <= eps certain; s*og > eps possible only when og > 1 (duplicates)
        need_exact = (og > 1.0f);
    } else {
        float m = d_nh[i] * d_nl[j] + d_nl[i] * d_nh[j] + 4e-6f;
        need_exact = fabsf(so * og - EPS) < m * og + 1e-6f;
        if (!need_exact) purif = (so * og > EPS) ? og : 0.f;
    }
    if (need_exact) {
        int idx = atomicAdd(&d_necand, 1);
        if (idx < ECAND_MAX) d_ecand[idx] = e;
        purif = 0.f;   // will be overwritten by edge_exact_kernel
    }
    d_val[e] = so + purif;
}

// Warp-collective fp64 exact recompute for the listed edges
__global__ void edge_exact_kernel(const int* __restrict__ oi,
                                  const float* __restrict__ out, int E) {
    int nc = d_necand;
    if (nc > ECAND_MAX) nc = ECAND_MAX;
    int gw = (blockIdx.x * blockDim.x + threadIdx.x) >> 5;
    int lane = threadIdx.x & 31;
    int nw = (gridDim.x * blockDim.x) >> 5;
    for (int c = gw; c < nc; c += nw) {
        int e = d_ecand[c];
        int i = oi[e], j = oi[E + e];
        const float* yi = d_Yf + (size_t)i * KK;
        const float* yj = d_Yf + (size_t)j * KK;
        double a = 0.0;
        for (int k = lane; k < KK; k += 32) a += (double)yi[k] * (double)yj[k];
#pragma unroll
        for (int o = 16; o > 0; o >>= 1) a += __shfl_xor_sync(0xffffffffu, a, o);
        if (lane == 0) {
            float s = (float)a;
            float og = d_og[(size_t)i * NN + j];
            float so = out[(size_t)i * NN + j];
            d_val[e] = so + ((s * og > EPS) ? og : 0.f);
        }
    }
}

__global__ void edge_fix_b(const int* __restrict__ oi, float* __restrict__ out, int E) {
    int e = blockIdx.x * blockDim.x + threadIdx.x;
    if (e >= E) return;
    out[(size_t)oi[e] * NN + oi[E + e]] = d_val[e];
}

// ---------------------------------------------------------------------------
extern "C" void kernel_launch(void* const* d_in, const int* in_sizes, int n_in,
                              void* d_out, int out_size) {
    const float* x  = (const float*)d_in[0];
    const int*   oi = (const int*)d_in[1];
    const float* ow = (const float*)d_in[2];
    const float* wp = (const float*)d_in[3];
    float* out = (float*)d_out;
    int E = in_sizes[2];

    cudaFuncSetAttribute(gemm_hmma_kernel,
                         cudaFuncAttributeMaxDynamicSharedMemorySize,
                         STAGES * STAGE_BYTES);

    zero_edges_kernel<<<(E + 255) / 256, 256>>>(oi, E);
    scatter_kernel<<<(E + 255) / 256, 256>>>(oi, ow, E);
    buildY_kernel<<<NN, DD>>>(x, wp);
    gemm_hmma_kernel<<<NTRI, NTHREADS, STAGES * STAGE_BYTES>>>(out);
    patch_kernel<<<256, 256>>>(out);
    edge_fix_a<<<(E + 255) / 256, 256>>>(oi, out, E);
    edge_exact_kernel<<<128, 256>>>(oi, out, E);
    edge_fix_b<<<(E + 255) / 256, 256>>>(oi, out, E);
}